// round 2
// baseline (speedup 1.0000x reference)
#include <cuda_runtime.h>
#include <math.h>

#define TT 512
#define NB 32
#define HID 1024
#define G4 4096

// scratch (device globals; no allocation allowed)
__device__ float g_xg[(size_t)TT * NB * G4];   // [t][b][j]
__device__ float g_W2s[256 * HID * 16];        // [tile][u][c], c=g*4+uu
__device__ float g_W1s[256 * 512 * 16];        // [tile][p][c]
__device__ float g_m[(size_t)TT * HID * NB];   // [t][u][b]
__device__ float g_h0t[512 * NB];              // [p][b]
__device__ float g_ct[HID * NB];               // [u][b]

// ---------------- prep: tile w_hh into W1s, transpose h0, c0 ----------------
__global__ void __launch_bounds__(256) prep_kernel(const float* __restrict__ whh,
                                                   const float* __restrict__ h0,
                                                   const float* __restrict__ c0) {
    const int total = 2097152 + 16384 + 32768;
    for (int i = blockIdx.x * blockDim.x + threadIdx.x; i < total;
         i += gridDim.x * blockDim.x) {
        if (i < 2097152) {
            int j = i >> 9, p = i & 511;
            int g = j >> 10, n = j & 1023;
            g_W1s[(((n >> 2) * 512) + p) * 16 + ((g << 2) | (n & 3))] = whh[i];
        } else if (i < 2097152 + 16384) {
            int e = i - 2097152;                      // e = p*32+b
            g_h0t[e] = h0[(e & 31) * 512 + (e >> 5)];
        } else {
            int e = i - 2097152 - 16384;              // e = u*32+b
            g_ct[e] = c0[(e & 31) * 1024 + (e >> 5)];
        }
    }
}

// ------------- W2 = w_hh(4096x512) @ w_hr(512x1024) -> tiled g_W2s ----------
__global__ void __launch_bounds__(256) w2_gemm_kernel(const float* __restrict__ whh,
                                                      const float* __restrict__ whr) {
    __shared__ float As[16][68];
    __shared__ float Bs[16][68];
    const int tid = threadIdx.x;
    const int j0 = blockIdx.y * 64;   // gate-row
    const int u0 = blockIdx.x * 64;   // K-dim of step
    const int lr = tid >> 2, lk = (tid & 3) << 2;
    const int brow = tid >> 4, bcol = (tid & 15) << 2;
    const int tr = tid >> 4, tc = tid & 15;
    float acc[4][4];
#pragma unroll
    for (int i = 0; i < 4; i++)
#pragma unroll
        for (int j = 0; j < 4; j++) acc[i][j] = 0.f;

    for (int k0 = 0; k0 < 512; k0 += 16) {
        float4 a = *(const float4*)(whh + (size_t)(j0 + lr) * 512 + k0 + lk);
        float4 b = *(const float4*)(whr + (size_t)(k0 + brow) * 1024 + u0 + bcol);
        __syncthreads();
        As[lk + 0][lr] = a.x; As[lk + 1][lr] = a.y;
        As[lk + 2][lr] = a.z; As[lk + 3][lr] = a.w;
        *(float4*)&Bs[brow][bcol] = b;
        __syncthreads();
#pragma unroll
        for (int kk = 0; kk < 16; kk++) {
            float4 av = *(float4*)&As[kk][tr * 4];
            float4 bv = *(float4*)&Bs[kk][tc * 4];
            float ar[4] = {av.x, av.y, av.z, av.w};
            float br[4] = {bv.x, bv.y, bv.z, bv.w};
#pragma unroll
            for (int i = 0; i < 4; i++)
#pragma unroll
                for (int j = 0; j < 4; j++)
                    acc[i][j] = fmaf(ar[i], br[j], acc[i][j]);
        }
    }
#pragma unroll
    for (int i = 0; i < 4; i++) {
        int j = j0 + tr * 4 + i;
        int g = j >> 10, n = j & 1023;
        int tile = n >> 2, cc = (g << 2) | (n & 3);
#pragma unroll
        for (int jj = 0; jj < 4; jj++) {
            int u = u0 + tc * 4 + jj;
            g_W2s[((size_t)tile * HID + u) * 16 + cc] = acc[i][jj];
        }
    }
}

// ----- x_gates: C[16384][4096] = input[16384][512] @ w_ih^T + bias ----------
__global__ void __launch_bounds__(256) xg_gemm_kernel(const float* __restrict__ A,
                                                      const float* __restrict__ Bw,
                                                      const float* __restrict__ bias) {
    __shared__ float As[16][132];
    __shared__ float Bs[16][132];
    const int tid = threadIdx.x;
    const int r0 = blockIdx.y * 128;
    const int c0 = blockIdx.x * 128;
    const int lr = tid >> 2, lk = (tid & 3) << 2;
    const int tr = tid >> 4, tc = tid & 15;
    float acc[8][8];
#pragma unroll
    for (int i = 0; i < 8; i++)
#pragma unroll
        for (int j = 0; j < 8; j++) acc[i][j] = 0.f;

    for (int k0 = 0; k0 < 512; k0 += 16) {
        float4 a0 = *(const float4*)(A + (size_t)(r0 + lr) * 512 + k0 + lk);
        float4 a1 = *(const float4*)(A + (size_t)(r0 + lr + 64) * 512 + k0 + lk);
        float4 b0 = *(const float4*)(Bw + (size_t)(c0 + lr) * 512 + k0 + lk);
        float4 b1 = *(const float4*)(Bw + (size_t)(c0 + lr + 64) * 512 + k0 + lk);
        __syncthreads();
        As[lk + 0][lr] = a0.x; As[lk + 1][lr] = a0.y; As[lk + 2][lr] = a0.z; As[lk + 3][lr] = a0.w;
        As[lk + 0][lr + 64] = a1.x; As[lk + 1][lr + 64] = a1.y; As[lk + 2][lr + 64] = a1.z; As[lk + 3][lr + 64] = a1.w;
        Bs[lk + 0][lr] = b0.x; Bs[lk + 1][lr] = b0.y; Bs[lk + 2][lr] = b0.z; Bs[lk + 3][lr] = b0.w;
        Bs[lk + 0][lr + 64] = b1.x; Bs[lk + 1][lr + 64] = b1.y; Bs[lk + 2][lr + 64] = b1.z; Bs[lk + 3][lr + 64] = b1.w;
        __syncthreads();
#pragma unroll
        for (int kk = 0; kk < 16; kk++) {
            float ar[8], br[8];
            *(float4*)&ar[0] = *(float4*)&As[kk][tr * 4];
            *(float4*)&ar[4] = *(float4*)&As[kk][64 + tr * 4];
            *(float4*)&br[0] = *(float4*)&Bs[kk][tc * 4];
            *(float4*)&br[4] = *(float4*)&Bs[kk][64 + tc * 4];
#pragma unroll
            for (int i = 0; i < 8; i++)
#pragma unroll
                for (int j = 0; j < 8; j++)
                    acc[i][j] = fmaf(ar[i], br[j], acc[i][j]);
        }
    }
#pragma unroll
    for (int i = 0; i < 8; i++) {
        int row = r0 + ((i < 4) ? (tr * 4 + i) : (64 + tr * 4 + (i - 4)));
#pragma unroll
        for (int half = 0; half < 2; half++) {
            int col = c0 + half * 64 + tc * 4;
            float4 v;
            v.x = acc[i][half * 4 + 0] + bias[col + 0];
            v.y = acc[i][half * 4 + 1] + bias[col + 1];
            v.z = acc[i][half * 4 + 2] + bias[col + 2];
            v.w = acc[i][half * 4 + 3] + bias[col + 3];
            *(float4*)(g_xg + (size_t)row * G4 + col) = v;
        }
    }
}

// --------------------------- one recurrence step ----------------------------
// K=512: t=0 (W1s, h0t). K=1024: t>=1 (W2s, m[t-1]).
// 256 CTAs: tile = 4 hidden units x 4 gates (16 cols) x 32 batches.
template <int K>
__global__ void __launch_bounds__(256) lstm_step_kernel(int t) {
    __shared__ float part[8 * 16 * 32];
    __shared__ float gs[16 * 32];
    const int tid = threadIdx.x;
    const int tile = blockIdx.x;
    const int warp = tid >> 5, lane = tid & 31;
    constexpr int KC = K / 8;

    const float* W = (K == 512) ? g_W1s : g_W2s;
    const float* mprev = (K == 512) ? g_h0t : (g_m + (size_t)(t - 1) * (HID * NB));
    const float* xg_t = g_xg + (size_t)t * (NB * G4);

    const float* mp = mprev + warp * KC * 32 + lane;
    const float4* wrow = (const float4*)W + ((size_t)tile * K + warp * KC) * 4;

    float acc[16];
#pragma unroll
    for (int c = 0; c < 16; c++) acc[c] = 0.f;

#pragma unroll 4
    for (int k = 0; k < KC; k++) {
        float mv = mp[k * 32];
        float4 w0 = wrow[k * 4 + 0];
        float4 w1 = wrow[k * 4 + 1];
        float4 w2 = wrow[k * 4 + 2];
        float4 w3 = wrow[k * 4 + 3];
        acc[0]  = fmaf(w0.x, mv, acc[0]);  acc[1]  = fmaf(w0.y, mv, acc[1]);
        acc[2]  = fmaf(w0.z, mv, acc[2]);  acc[3]  = fmaf(w0.w, mv, acc[3]);
        acc[4]  = fmaf(w1.x, mv, acc[4]);  acc[5]  = fmaf(w1.y, mv, acc[5]);
        acc[6]  = fmaf(w1.z, mv, acc[6]);  acc[7]  = fmaf(w1.w, mv, acc[7]);
        acc[8]  = fmaf(w2.x, mv, acc[8]);  acc[9]  = fmaf(w2.y, mv, acc[9]);
        acc[10] = fmaf(w2.z, mv, acc[10]); acc[11] = fmaf(w2.w, mv, acc[11]);
        acc[12] = fmaf(w3.x, mv, acc[12]); acc[13] = fmaf(w3.y, mv, acc[13]);
        acc[14] = fmaf(w3.z, mv, acc[14]); acc[15] = fmaf(w3.w, mv, acc[15]);
    }
#pragma unroll
    for (int c = 0; c < 16; c++) part[(warp * 16 + c) * 32 + lane] = acc[c];
    __syncthreads();

#pragma unroll
    for (int rep = 0; rep < 2; rep++) {
        int idx = tid + rep * 256;
        int c = idx >> 5, b = idx & 31;
        float s = part[c * 32 + b];
#pragma unroll
        for (int w = 1; w < 8; w++) s += part[(w * 16 + c) * 32 + b];
        gs[c * 32 + b] = s;
    }
    __syncthreads();

    if (tid < 128) {
        int g = tid >> 5, b = tid & 31;
        float4 xv = *(const float4*)(xg_t + (size_t)b * G4 + g * 1024 + tile * 4);
        gs[(g * 4 + 0) * 32 + b] += xv.x;
        gs[(g * 4 + 1) * 32 + b] += xv.y;
        gs[(g * 4 + 2) * 32 + b] += xv.z;
        gs[(g * 4 + 3) * 32 + b] += xv.w;
    }
    __syncthreads();

    if (tid < 128) {
        int uu = tid >> 5, b = tid & 31;
        int u = tile * 4 + uu;
        float gi = gs[(0 + uu) * 32 + b];
        float gf = gs[(4 + uu) * 32 + b];
        float gg = gs[(8 + uu) * 32 + b];
        float go = gs[(12 + uu) * 32 + b];
        float c0v = g_ct[u * 32 + b];
        float si = 1.f / (1.f + expf(-gi));
        float sf = 1.f / (1.f + expf(-gf));
        float so = 1.f / (1.f + expf(-go));
        float c1 = sf * c0v + si * tanhf(gg);
        g_ct[u * 32 + b] = c1;
        g_m[(size_t)t * (HID * NB) + u * 32 + b] = so * tanhf(c1);
    }
}

// ------ y[t][b][p] = sum_u m[t][u][b] * w_hr[p][u]  (all t in parallel) -----
__global__ void __launch_bounds__(256) y_gemm_kernel(const float* __restrict__ whr,
                                                     float* __restrict__ out) {
    __shared__ float As[16 * 32];      // m chunk, flat [k][b]
    __shared__ float Bs[16][132];      // whr chunk [k][p]
    const int tid = threadIdx.x;
    const int t = blockIdx.x;
    const int p0 = blockIdx.y * 128;
    const int tr = tid >> 5;           // b-group (0..7)
    const int tc = tid & 31;           // p-group (0..31)
    float acc[4][4];
#pragma unroll
    for (int i = 0; i < 4; i++)
#pragma unroll
        for (int j = 0; j < 4; j++) acc[i][j] = 0.f;

    const float4* msrc = (const float4*)(g_m + (size_t)t * (HID * NB));
    const int lp = tid >> 1, ch = tid & 1;

    for (int k0 = 0; k0 < HID; k0 += 16) {
        float4 a;
        if (tid < 128) a = msrc[k0 * 8 + tid];
        const float4* brow = (const float4*)(whr + (size_t)(p0 + lp) * HID + k0);
        float4 bv0 = brow[ch * 2 + 0];
        float4 bv1 = brow[ch * 2 + 1];
        __syncthreads();
        if (tid < 128) ((float4*)As)[tid] = a;
        Bs[ch * 8 + 0][lp] = bv0.x; Bs[ch * 8 + 1][lp] = bv0.y;
        Bs[ch * 8 + 2][lp] = bv0.z; Bs[ch * 8 + 3][lp] = bv0.w;
        Bs[ch * 8 + 4][lp] = bv1.x; Bs[ch * 8 + 5][lp] = bv1.y;
        Bs[ch * 8 + 6][lp] = bv1.z; Bs[ch * 8 + 7][lp] = bv1.w;
        __syncthreads();
#pragma unroll
        for (int kk = 0; kk < 16; kk++) {
            float4 av = *(float4*)&As[kk * 32 + tr * 4];
            float4 bv = *(float4*)&Bs[kk][tc * 4];
            float ar[4] = {av.x, av.y, av.z, av.w};
            float br[4] = {bv.x, bv.y, bv.z, bv.w};
#pragma unroll
            for (int i = 0; i < 4; i++)
#pragma unroll
                for (int j = 0; j < 4; j++)
                    acc[i][j] = fmaf(ar[i], br[j], acc[i][j]);
        }
    }
#pragma unroll
    for (int i = 0; i < 4; i++) {
        int b = tr * 4 + i;
        float4 v = {acc[i][0], acc[i][1], acc[i][2], acc[i][3]};
        *(float4*)(out + (size_t)t * (NB * 512) + (size_t)b * 512 + p0 + tc * 4) = v;
    }
}

// ---- outputs: y already in place; append hT (=y[T-1]) and cT ----
__global__ void __launch_bounds__(256) finalize_kernel(float* __restrict__ out) {
    int i = blockIdx.x * blockDim.x + threadIdx.x;
    const size_t Y = (size_t)TT * NB * 512;      // 8388608
    if (i < 16384) {
        out[Y + i] = out[(size_t)511 * (NB * 512) + i];   // hT[b][p]
    } else if (i < 16384 + 32768) {
        int e = i - 16384;                                // e = b*1024+u
        out[Y + 16384 + e] = g_ct[(e & 1023) * 32 + (e >> 10)];
    }
}

extern "C" void kernel_launch(void* const* d_in, const int* in_sizes, int n_in,
                              void* d_out, int out_size) {
    const float* input = (const float*)d_in[0];
    const float* h0    = (const float*)d_in[1];
    const float* c0    = (const float*)d_in[2];
    const float* w_ih  = (const float*)d_in[3];
    const float* w_hh  = (const float*)d_in[4];
    const float* bias  = (const float*)d_in[5];
    const float* w_hr  = (const float*)d_in[6];
    float* out = (float*)d_out;

    prep_kernel<<<2048, 256>>>(w_hh, h0, c0);
    w2_gemm_kernel<<<dim3(16, 64), 256>>>(w_hh, w_hr);
    xg_gemm_kernel<<<dim3(32, 128), 256>>>(input, w_ih, bias);

    lstm_step_kernel<512><<<256, 256>>>(0);
    for (int t = 1; t < TT; t++)
        lstm_step_kernel<1024><<<256, 256>>>(t);

    y_gemm_kernel<<<dim3(TT, 4), 256>>>(w_hr, out);
    finalize_kernel<<<192, 256>>>(out);
}

// round 3
// speedup vs baseline: 2.2644x; 2.2644x over previous
#include <cuda_runtime.h>
#include <math.h>

#define TT 512
#define NB 32
#define HID 1024
#define G4 4096

// scratch (device globals; no allocation allowed)
__device__ float g_xgT[(size_t)G4 * (TT * NB)];   // [j][t*32+b]  256 MB
__device__ float g_W2s[128 * HID * 32];           // [cta][u][c], c=g*8+uu
__device__ float g_W1s[128 * 512 * 32];           // [cta][p][c]
__device__ float g_m[(size_t)TT * HID * NB];      // [t][u][b]
__device__ float g_h0t[512 * NB];                 // [p][b]
__device__ float g_ct[HID * NB];                  // [u][b]
__device__ unsigned g_bar;

// ---------------- packed f32x2 helpers (sm_100a) ----------------
__device__ __forceinline__ long long pk2(float x, float y) {
    long long r;
    asm("mov.b64 %0, {%1, %2};" : "=l"(r) : "r"(__float_as_uint(x)), "r"(__float_as_uint(y)));
    return r;
}
__device__ __forceinline__ long long f2fma(long long a, long long b, long long c) {
    long long d;
    asm("fma.rn.f32x2 %0, %1, %2, %3;" : "=l"(d) : "l"(a), "l"(b), "l"(c));
    return d;
}
__device__ __forceinline__ float2 up2(long long v) {
    unsigned lo, hi;
    asm("mov.b64 {%0, %1}, %2;" : "=r"(lo), "=r"(hi) : "l"(v));
    return make_float2(__uint_as_float(lo), __uint_as_float(hi));
}

// ---------------- prep: tile w_hh into W1s, transpose h0, c0, reset bar -----
__global__ void __launch_bounds__(256) prep_kernel(const float* __restrict__ whh,
                                                   const float* __restrict__ h0,
                                                   const float* __restrict__ c0) {
    if (blockIdx.x == 0 && threadIdx.x == 0) g_bar = 0u;
    const int total = 2097152 + 16384 + 32768;
    for (int i = blockIdx.x * blockDim.x + threadIdx.x; i < total;
         i += gridDim.x * blockDim.x) {
        if (i < 2097152) {
            int j = i >> 9, p = i & 511;
            int g = j >> 10, n = j & 1023;
            g_W1s[(((size_t)(n >> 3) * 512) + p) * 32 + ((g << 3) | (n & 7))] = whh[i];
        } else if (i < 2097152 + 16384) {
            int e = i - 2097152;                      // e = p*32+b
            g_h0t[e] = h0[(e & 31) * 512 + (e >> 5)];
        } else {
            int e = i - 2097152 - 16384;              // e = u*32+b
            g_ct[e] = c0[(e & 31) * 1024 + (e >> 5)];
        }
    }
}

// ------------- W2 = w_hh(4096x512) @ w_hr(512x1024) -> tiled g_W2s ----------
__global__ void __launch_bounds__(256) w2_gemm_kernel(const float* __restrict__ whh,
                                                      const float* __restrict__ whr) {
    __shared__ float As[16][68];
    __shared__ float Bs[16][68];
    const int tid = threadIdx.x;
    const int j0 = blockIdx.y * 64;   // gate-row
    const int u0 = blockIdx.x * 64;   // K-dim of step
    const int lr = tid >> 2, lk = (tid & 3) << 2;
    const int brow = tid >> 4, bcol = (tid & 15) << 2;
    const int tr = tid >> 4, tc = tid & 15;
    float acc[4][4];
#pragma unroll
    for (int i = 0; i < 4; i++)
#pragma unroll
        for (int j = 0; j < 4; j++) acc[i][j] = 0.f;

    for (int k0 = 0; k0 < 512; k0 += 16) {
        float4 a = *(const float4*)(whh + (size_t)(j0 + lr) * 512 + k0 + lk);
        float4 b = *(const float4*)(whr + (size_t)(k0 + brow) * 1024 + u0 + bcol);
        __syncthreads();
        As[lk + 0][lr] = a.x; As[lk + 1][lr] = a.y;
        As[lk + 2][lr] = a.z; As[lk + 3][lr] = a.w;
        *(float4*)&Bs[brow][bcol] = b;
        __syncthreads();
#pragma unroll
        for (int kk = 0; kk < 16; kk++) {
            float4 av = *(float4*)&As[kk][tr * 4];
            float4 bv = *(float4*)&Bs[kk][tc * 4];
            float ar[4] = {av.x, av.y, av.z, av.w};
            float br[4] = {bv.x, bv.y, bv.z, bv.w};
#pragma unroll
            for (int i = 0; i < 4; i++)
#pragma unroll
                for (int j = 0; j < 4; j++)
                    acc[i][j] = fmaf(ar[i], br[j], acc[i][j]);
        }
    }
#pragma unroll
    for (int i = 0; i < 4; i++) {
        int j = j0 + tr * 4 + i;
        int g = j >> 10, n = j & 1023;
        int cc = (g << 3) | (n & 7);
#pragma unroll
        for (int jj = 0; jj < 4; jj++) {
            int u = u0 + tc * 4 + jj;
            g_W2s[((size_t)(n >> 3) * 1024 + u) * 32 + cc] = acc[i][jj];
        }
    }
}

// ----- xgT: C[j][r] = w_ih[j][:] . input[r][:] + bias[j], r = t*32+b --------
__global__ void __launch_bounds__(256) xg_gemm_kernel(const float* __restrict__ Wih,
                                                      const float* __restrict__ inp,
                                                      const float* __restrict__ bias) {
    __shared__ float As[16][132];   // [k][j]
    __shared__ float Bs[16][132];   // [k][r]
    const int tid = threadIdx.x;
    const int j0 = blockIdx.y * 128;
    const int r0 = blockIdx.x * 128;
    const int lr = tid >> 2, lk = (tid & 3) << 2;
    const int tr = tid >> 4, tc = tid & 15;
    long long acc[8][4];
#pragma unroll
    for (int i = 0; i < 8; i++)
#pragma unroll
        for (int p = 0; p < 4; p++) acc[i][p] = 0ll;

    for (int k0 = 0; k0 < 512; k0 += 16) {
        float4 a0 = *(const float4*)(Wih + (size_t)(j0 + lr) * 512 + k0 + lk);
        float4 a1 = *(const float4*)(Wih + (size_t)(j0 + lr + 64) * 512 + k0 + lk);
        float4 b0 = *(const float4*)(inp + (size_t)(r0 + lr) * 512 + k0 + lk);
        float4 b1 = *(const float4*)(inp + (size_t)(r0 + lr + 64) * 512 + k0 + lk);
        __syncthreads();
        As[lk + 0][lr] = a0.x; As[lk + 1][lr] = a0.y; As[lk + 2][lr] = a0.z; As[lk + 3][lr] = a0.w;
        As[lk + 0][lr + 64] = a1.x; As[lk + 1][lr + 64] = a1.y; As[lk + 2][lr + 64] = a1.z; As[lk + 3][lr + 64] = a1.w;
        Bs[lk + 0][lr] = b0.x; Bs[lk + 1][lr] = b0.y; Bs[lk + 2][lr] = b0.z; Bs[lk + 3][lr] = b0.w;
        Bs[lk + 0][lr + 64] = b1.x; Bs[lk + 1][lr + 64] = b1.y; Bs[lk + 2][lr + 64] = b1.z; Bs[lk + 3][lr + 64] = b1.w;
        __syncthreads();
#pragma unroll
        for (int kk = 0; kk < 16; kk++) {
            float ar[8];
            *(float4*)&ar[0] = *(float4*)&As[kk][tr * 4];
            *(float4*)&ar[4] = *(float4*)&As[kk][64 + tr * 4];
            longlong2 bp0 = *(const longlong2*)&Bs[kk][tc * 4];
            longlong2 bp1 = *(const longlong2*)&Bs[kk][64 + tc * 4];
            long long ad[8];
#pragma unroll
            for (int i = 0; i < 8; i++) ad[i] = pk2(ar[i], ar[i]);
#pragma unroll
            for (int i = 0; i < 8; i++) {
                acc[i][0] = f2fma(bp0.x, ad[i], acc[i][0]);
                acc[i][1] = f2fma(bp0.y, ad[i], acc[i][1]);
                acc[i][2] = f2fma(bp1.x, ad[i], acc[i][2]);
                acc[i][3] = f2fma(bp1.y, ad[i], acc[i][3]);
            }
        }
    }
#pragma unroll
    for (int i = 0; i < 8; i++) {
        int row = j0 + ((i < 4) ? (tr * 4 + i) : (64 + tr * 4 + (i - 4)));
        float bj = bias[row];
#pragma unroll
        for (int half = 0; half < 2; half++) {
            float2 v0 = up2(acc[i][half * 2 + 0]);
            float2 v1 = up2(acc[i][half * 2 + 1]);
            float4 v = {v0.x + bj, v0.y + bj, v1.x + bj, v1.y + bj};
            *(float4*)(g_xgT + (size_t)row * (TT * NB) + r0 + half * 64 + tc * 4) = v;
        }
    }
}

// ---------------- persistent recurrence: all 512 steps ----------------------
// 128 CTAs x 512 threads, 1 CTA/SM. CTA = 8 units x 4 gates (32 cols) x 32 b.
// Weights resident in SMEM; grid barrier via atomic counter each step.
__global__ void __launch_bounds__(512) lstm_seq_kernel() {
    extern __shared__ float sh[];
    float* ws   = sh;            // 32768 floats: [k][c]
    float* part = sh + 32768;    // 16384 floats: [warp][c][b]
    float* gs   = part + 16384;  // 1024 floats:  [c][b]
    const int tid = threadIdx.x;
    const int cta = blockIdx.x;
    const int warp = tid >> 5, lane = tid & 31;
    const int cg = lane >> 3, bg = lane & 7;   // cg: col-group(8 cols), bg: b-group(4 b)
    const int uu = tid >> 5, bb = tid & 31;    // for tid<256: unit-in-tile, batch

    // load this CTA's W2 tile (1024 x 32) into SMEM once
    {
        const float4* src = (const float4*)(g_W2s + (size_t)cta * 32768);
        float4* dst = (float4*)ws;
#pragma unroll
        for (int i = 0; i < 16; i++) dst[tid + i * 512] = src[tid + i * 512];
    }
    float creg = 0.f;
    if (tid < 256) creg = g_ct[(cta * 8 + uu) * 32 + bb];
    __syncthreads();

    for (int t = 0; t < TT; t++) {
        long long acc[4][4];   // [b-offset q][col-pair p]
#pragma unroll
        for (int q = 0; q < 4; q++)
#pragma unroll
            for (int p = 0; p < 4; p++) acc[q][p] = 0ll;

        if (t == 0) {
            // K=512: weights from global g_W1s, m = h0t
            const float* wbase = g_W1s + (size_t)cta * 512 * 32;
            const int k0 = warp * 32;
#pragma unroll 4
            for (int kk = 0; kk < 32; kk++) {
                int k = k0 + kk;
                float4 mv = __ldcg((const float4*)(g_h0t + k * 32 + bg * 4));
                longlong2 w01 = __ldcg((const longlong2*)(wbase + k * 32 + cg * 8));
                longlong2 w23 = __ldcg((const longlong2*)(wbase + k * 32 + cg * 8 + 4));
                long long md[4] = {pk2(mv.x, mv.x), pk2(mv.y, mv.y),
                                   pk2(mv.z, mv.z), pk2(mv.w, mv.w)};
#pragma unroll
                for (int q = 0; q < 4; q++) {
                    acc[q][0] = f2fma(w01.x, md[q], acc[q][0]);
                    acc[q][1] = f2fma(w01.y, md[q], acc[q][1]);
                    acc[q][2] = f2fma(w23.x, md[q], acc[q][2]);
                    acc[q][3] = f2fma(w23.y, md[q], acc[q][3]);
                }
            }
        } else {
            // K=1024: weights from SMEM, m = g_m[t-1]
            const float* mp = g_m + (size_t)(t - 1) * (HID * NB);
            const int k0 = warp * 64;
#pragma unroll 4
            for (int kk = 0; kk < 64; kk++) {
                int k = k0 + kk;
                float4 mv = __ldcg((const float4*)(mp + k * 32 + bg * 4));
                longlong2 w01 = *(const longlong2*)(ws + k * 32 + cg * 8);
                longlong2 w23 = *(const longlong2*)(ws + k * 32 + cg * 8 + 4);
                long long md[4] = {pk2(mv.x, mv.x), pk2(mv.y, mv.y),
                                   pk2(mv.z, mv.z), pk2(mv.w, mv.w)};
#pragma unroll
                for (int q = 0; q < 4; q++) {
                    acc[q][0] = f2fma(w01.x, md[q], acc[q][0]);
                    acc[q][1] = f2fma(w01.y, md[q], acc[q][1]);
                    acc[q][2] = f2fma(w23.x, md[q], acc[q][2]);
                    acc[q][3] = f2fma(w23.y, md[q], acc[q][3]);
                }
            }
        }

        // store partials: part[warp][c][b]
#pragma unroll
        for (int p = 0; p < 4; p++)
#pragma unroll
            for (int q = 0; q < 4; q++) {
                float2 v = up2(acc[q][p]);
                int c0 = cg * 8 + p * 2;
                part[warp * 1024 + c0 * 32 + bg * 4 + q] = v.x;
                part[warp * 1024 + (c0 + 1) * 32 + bg * 4 + q] = v.y;
            }
        __syncthreads();

        // reduce 16 partials + add xg
#pragma unroll
        for (int rep = 0; rep < 2; rep++) {
            int o = tid + rep * 512;
            int c = o >> 5, b = o & 31;
            float s = part[o];
#pragma unroll
            for (int w = 1; w < 16; w++) s += part[w * 1024 + o];
            int j = (c >> 3) * 1024 + cta * 8 + (c & 7);
            s += __ldcg(&g_xgT[(size_t)j * (TT * NB) + t * 32 + b]);
            gs[o] = s;
        }
        __syncthreads();

        // activations + state update (tid<256: 8 units x 32 batches)
        if (tid < 256) {
            float gi = gs[(0 * 8 + uu) * 32 + bb];
            float gf = gs[(1 * 8 + uu) * 32 + bb];
            float gg = gs[(2 * 8 + uu) * 32 + bb];
            float go = gs[(3 * 8 + uu) * 32 + bb];
            float si = 1.f / (1.f + expf(-gi));
            float sf = 1.f / (1.f + expf(-gf));
            float so = 1.f / (1.f + expf(-go));
            creg = sf * creg + si * tanhf(gg);
            g_m[(size_t)t * (HID * NB) + (cta * 8 + uu) * 32 + bb] = so * tanhf(creg);
            __threadfence();
        }
        __syncthreads();

        // grid barrier (monotonic counter; reset by prep each launch)
        if (tid == 0) {
            atomicAdd(&g_bar, 1u);
            const unsigned target = 128u * (t + 1);
            while (*(volatile unsigned*)&g_bar < target) { }
        }
        __syncthreads();
    }

    if (tid < 256) g_ct[(cta * 8 + uu) * 32 + bb] = creg;
}

// ------ y[t][b][p] = sum_u m[t][u][b] * w_hr[p][u]  (all t in parallel) -----
__global__ void __launch_bounds__(256) y_gemm_kernel(const float* __restrict__ whr,
                                                     float* __restrict__ out) {
    __shared__ float As[16 * 32];      // m chunk, flat [k][b]
    __shared__ float Bs[16][132];      // whr chunk [k][p]
    const int tid = threadIdx.x;
    const int t = blockIdx.x;
    const int p0 = blockIdx.y * 128;
    const int tr = tid >> 5;           // b-group (0..7)
    const int tc = tid & 31;           // p-group (0..31)
    float acc[4][4];
#pragma unroll
    for (int i = 0; i < 4; i++)
#pragma unroll
        for (int j = 0; j < 4; j++) acc[i][j] = 0.f;

    const float4* msrc = (const float4*)(g_m + (size_t)t * (HID * NB));
    const int lp = tid >> 1, ch = tid & 1;

    for (int k0 = 0; k0 < HID; k0 += 16) {
        float4 a;
        if (tid < 128) a = msrc[k0 * 8 + tid];
        const float4* brow = (const float4*)(whr + (size_t)(p0 + lp) * HID + k0);
        float4 bv0 = brow[ch * 2 + 0];
        float4 bv1 = brow[ch * 2 + 1];
        __syncthreads();
        if (tid < 128) ((float4*)As)[tid] = a;
        Bs[ch * 8 + 0][lp] = bv0.x; Bs[ch * 8 + 1][lp] = bv0.y;
        Bs[ch * 8 + 2][lp] = bv0.z; Bs[ch * 8 + 3][lp] = bv0.w;
        Bs[ch * 8 + 4][lp] = bv1.x; Bs[ch * 8 + 5][lp] = bv1.y;
        Bs[ch * 8 + 6][lp] = bv1.z; Bs[ch * 8 + 7][lp] = bv1.w;
        __syncthreads();
#pragma unroll
        for (int kk = 0; kk < 16; kk++) {
            float4 av = *(float4*)&As[kk * 32 + tr * 4];
            float4 bv = *(float4*)&Bs[kk][tc * 4];
            float ar[4] = {av.x, av.y, av.z, av.w};
            float br[4] = {bv.x, bv.y, bv.z, bv.w};
#pragma unroll
            for (int i = 0; i < 4; i++)
#pragma unroll
                for (int j = 0; j < 4; j++)
                    acc[i][j] = fmaf(ar[i], br[j], acc[i][j]);
        }
    }
#pragma unroll
    for (int i = 0; i < 4; i++) {
        int b = tr * 4 + i;
        float4 v = {acc[i][0], acc[i][1], acc[i][2], acc[i][3]};
        *(float4*)(out + (size_t)t * (NB * 512) + (size_t)b * 512 + p0 + tc * 4) = v;
    }
}

// ---- outputs: y already in place; append hT (=y[T-1]) and cT ----
__global__ void __launch_bounds__(256) finalize_kernel(float* __restrict__ out) {
    int i = blockIdx.x * blockDim.x + threadIdx.x;
    const size_t Y = (size_t)TT * NB * 512;      // 8388608
    if (i < 16384) {
        out[Y + i] = out[(size_t)511 * (NB * 512) + i];   // hT[b][p]
    } else if (i < 16384 + 32768) {
        int e = i - 16384;                                // e = b*1024+u
        out[Y + 16384 + e] = g_ct[(e & 1023) * 32 + (e >> 10)];
    }
}

extern "C" void kernel_launch(void* const* d_in, const int* in_sizes, int n_in,
                              void* d_out, int out_size) {
    const float* input = (const float*)d_in[0];
    const float* h0    = (const float*)d_in[1];
    const float* c0    = (const float*)d_in[2];
    const float* w_ih  = (const float*)d_in[3];
    const float* w_hh  = (const float*)d_in[4];
    const float* bias  = (const float*)d_in[5];
    const float* w_hr  = (const float*)d_in[6];
    float* out = (float*)d_out;

    cudaFuncSetAttribute(lstm_seq_kernel,
                         cudaFuncAttributeMaxDynamicSharedMemorySize, 200704);

    prep_kernel<<<2048, 256>>>(w_hh, h0, c0);
    w2_gemm_kernel<<<dim3(16, 64), 256>>>(w_hh, w_hr);
    xg_gemm_kernel<<<dim3(128, 32), 256>>>(w_ih, input, bias);

    lstm_seq_kernel<<<128, 512, 200704>>>();

    y_gemm_kernel<<<dim3(TT, 4), 256>>>(w_hr, out);
    finalize_kernel<<<192, 256>>>(out);
}